// round 10
// baseline (speedup 1.0000x reference)
#include <cuda_runtime.h>
#include <cuda_bf16.h>
#include <cstdint>

#define BATCH 4
#define NCLS 19
#define IMH 512
#define IMW 1024
#define HW (IMH * IMW)           // 524288 = 2^19
#define NPIX (BATCH * HW)
#define KTOP 256
#define EPSF 1e-6f

// ---------------- scratch (static device arrays; no allocation) ----------------
__device__ float         g_entropy[NPIX];
__device__ unsigned char g_label[NPIX];
__device__ float         g_score[NPIX];
__device__ unsigned int  g_cand[NPIX];         // compacted boundary-bin bit patterns
__device__ unsigned int  g_hist0[BATCH * 2048];
__device__ unsigned int  g_sel_k[BATCH];       // remaining k within boundary bin
__device__ unsigned int  g_sel_key[BATCH];     // level-0 bin (top 11 bits)
__device__ float         g_sum[BATCH];         // sum of values with prefix > key0
__device__ unsigned int  g_cnt[BATCH];
__device__ unsigned int  g_ncand[BATCH];
__device__ unsigned int  g_ctr[2 * BATCH];     // last-block counters per phase

// ---------------- block-wide descending radix-select -------------------------
// Finds bin (from highest down) where cumulative count crosses k.
// Exactly one thread writes *ret_bin/*ret_rem (caller must __syncthreads after).
template<int T, bool LDCG>
__device__ __forceinline__ void block_select(const unsigned int* __restrict__ h,
                                             int nbins, unsigned int k, int tid,
                                             unsigned int* s_scan,      // >= T/32
                                             unsigned int* ret_bin,
                                             unsigned int* ret_rem) {
    const int W = T / 32;
    int cs = nbins / T;
    int base = nbins - 1 - tid * cs;
    unsigned int csum = 0;
    for (int i = 0; i < cs; i++) csum += LDCG ? __ldcg(&h[base - i]) : h[base - i];

    unsigned int v = csum;
    #pragma unroll
    for (int off = 1; off < 32; off <<= 1) {
        unsigned int y = __shfl_up_sync(0xFFFFFFFFu, v, off);
        if ((tid & 31) >= off) v += y;
    }
    if ((tid & 31) == 31) s_scan[tid >> 5] = v;
    __syncthreads();
    if (tid < W) {
        unsigned int w = s_scan[tid];
        const unsigned int m = (W == 32) ? 0xFFFFFFFFu : ((1u << W) - 1u);
        #pragma unroll
        for (int off = 1; off < W; off <<= 1) {
            unsigned int y = __shfl_up_sync(m, w, off);
            if (tid >= off) w += y;
        }
        s_scan[tid] = w;
    }
    __syncthreads();
    unsigned int incl = v + ((tid >= 32) ? s_scan[(tid >> 5) - 1] : 0u);
    unsigned int excl = incl - csum;

    if (excl < k && k <= incl) {
        unsigned int run = excl;
        for (int i = 0; i < cs; i++) {
            unsigned int hv = LDCG ? __ldcg(&h[base - i]) : h[base - i];
            if (run < k && k <= run + hv) {
                *ret_bin = (unsigned int)(base - i);
                *ret_rem = k - run;
                break;
            }
            run += hv;
        }
    }
}

// ---------------- kernel 1: per-pixel entropy + argmax (float4, fused init) ----
__global__ void k_pixel(const float* __restrict__ logit) {
    if (blockIdx.x == 0) {
        int t = threadIdx.x;
        for (int i = t; i < 2048 * BATCH; i += 256) g_hist0[i] = 0;
        if (t < BATCH) {
            g_sel_k[t] = KTOP; g_sel_key[t] = 0;
            g_sum[t] = 0.0f; g_cnt[t] = 0; g_ncand[t] = 0;
        }
        if (t < 2 * BATCH) g_ctr[t] = 0;
    }

    int idx = blockIdx.x * blockDim.x + threadIdx.x;   // one float4 (4 pixels)
    int p4 = idx * 4;
    int b  = p4 >> 19;
    int hw = p4 & (HW - 1);
    const float4* base = (const float4*)(logit + (size_t)b * NCLS * HW + hw);
    const int planeStride = HW / 4;

    float4 ent  = make_float4(0.f, 0.f, 0.f, 0.f);
    float4 best = make_float4(-1.f, -1.f, -1.f, -1.f);
    int bc0 = 0, bc1 = 0, bc2 = 0, bc3 = 0;
    #pragma unroll
    for (int c = 0; c < NCLS; c++) {
        float4 p = base[c * planeStride];
        ent.x -= p.x * __logf(p.x + EPSF);
        ent.y -= p.y * __logf(p.y + EPSF);
        ent.z -= p.z * __logf(p.z + EPSF);
        ent.w -= p.w * __logf(p.w + EPSF);
        if (p.x > best.x) { best.x = p.x; bc0 = c; }
        if (p.y > best.y) { best.y = p.y; bc1 = c; }
        if (p.z > best.z) { best.z = p.z; bc2 = c; }
        if (p.w > best.w) { best.w = p.w; bc3 = c; }
    }
    float invLogC = 1.0f / __logf((float)NCLS);
    ent.x *= invLogC; ent.y *= invLogC; ent.z *= invLogC; ent.w *= invLogC;
    ((float4*)g_entropy)[idx] = ent;
    ((uchar4*)g_label)[idx] = make_uchar4((unsigned char)bc0, (unsigned char)bc1,
                                          (unsigned char)bc2, (unsigned char)bc3);
}

// ---------------- kernel 2: 3x3 region score + hist0 + fused select0 ----------
#define TBX 32
#define TBY 8
__global__ void k_region(void) {
    __shared__ float         s_ent[TBY + 2][TBX + 2];
    __shared__ unsigned char s_lab[TBY + 2][TBX + 2];
    __shared__ unsigned int  s_hist[2048];
    __shared__ float         s_T[48];           // impurity table
    __shared__ unsigned int  s_scan[8];
    __shared__ unsigned int  s_bin, s_rem;
    __shared__ int           s_last;

    int b  = blockIdx.z;
    int bx = blockIdx.x * TBX;
    int by = blockIdx.y * TBY;
    int tx = threadIdx.x, ty = threadIdx.y;
    int tid = ty * TBX + tx;

    for (int i = tid; i < 2048; i += 256) s_hist[i] = 0;

    if (tid < 48) {
        int nIdx = tid >> 4, c = tid & 15;
        float n = (nIdx == 0) ? 4.0f : (nIdx == 1) ? 6.0f : 9.0f;
        float val = 0.0f;
        if (c >= 1 && c <= 9) {
            float p = (float)c / n;
            val = -p * __logf(p + EPSF) * (1.0f / __logf((float)NCLS));
        }
        s_T[tid] = val;
    }

    const int TILE = (TBY + 2) * (TBX + 2);
    for (int i = tid; i < TILE; i += 256) {
        int ly = i / (TBX + 2), lx = i % (TBX + 2);
        int gy = by + ly - 1, gx = bx + lx - 1;
        bool ok = (gy >= 0 && gy < IMH && gx >= 0 && gx < IMW);
        int gidx = b * HW + gy * IMW + gx;
        s_ent[ly][lx] = ok ? g_entropy[gidx] : 0.0f;
        s_lab[ly][lx] = ok ? g_label[gidx] : (unsigned char)255;
    }
    __syncthreads();

    float entsum = 0.0f;
    unsigned long long accLo = 0ull;
    unsigned int accHi = 0u;
    int n = 0;
    #pragma unroll
    for (int dy = 0; dy < 3; dy++)
    #pragma unroll
        for (int dx = 0; dx < 3; dx++) {
            entsum += s_ent[ty + dy][tx + dx];
            int L = s_lab[ty + dy][tx + dx];
            if (L < 16)        { accLo += 1ull << (L * 4);        n++; }
            else if (L != 255) { accHi += 1u   << ((L - 16) * 4); n++; }
        }

    int nIdx = (n == 9) ? 2 : ((n == 6) ? 1 : 0);
    const float* T = s_T + nIdx * 16;
    float imp = 0.0f;
    #pragma unroll
    for (int c = 0; c < 16; c++) imp += T[(unsigned int)(accLo >> (c * 4)) & 15u];
    #pragma unroll
    for (int c = 0; c < 3; c++)  imp += T[(accHi >> (c * 4)) & 15u];

    float sc = entsum * (1.0f / 9.0f) * imp;
    g_score[b * HW + (by + ty) * IMW + (bx + tx)] = sc;

    unsigned int bits = __float_as_uint(sc);     // sc >= 0 => uint order == float order
    atomicAdd(&s_hist[bits >> 21], 1u);
    __syncthreads();
    for (int i = tid; i < 2048; i += 256) {
        unsigned int v = s_hist[i];
        if (v) atomicAdd(&g_hist0[b * 2048 + i], v);
    }

    __threadfence();
    __syncthreads();
    if (tid == 0) {
        unsigned int done = atomicAdd(&g_ctr[0 * BATCH + b], 1u);
        s_last = (done == gridDim.x * gridDim.y - 1);
    }
    __syncthreads();
    if (s_last) {
        block_select<256, true>(g_hist0 + b * 2048, 2048, KTOP, tid,
                                s_scan, &s_bin, &s_rem);
        __syncthreads();
        if (tid == 0) { g_sel_key[b] = s_bin; g_sel_k[b] = s_rem; }
    }
}

// ---------------- kernel 3: collect + compact + fused small top-k -------------
#define CB 128   // blocks per batch
#define CT 512   // threads per block
__global__ void k_collect(float* __restrict__ out) {
    __shared__ unsigned int s_hist[2048];
    __shared__ unsigned int s_scan[CT / 32];
    __shared__ float        s_wsum[CT / 32];
    __shared__ unsigned int s_wcnt[CT / 32];
    __shared__ unsigned int s_bin, s_rem;
    __shared__ int s_last;

    int b = blockIdx.y;
    int tid = threadIdx.x;
    int lane = tid & 31;
    unsigned int key0 = g_sel_key[b];
    const float4* sc = (const float4*)(g_score + b * HW);
    unsigned int* cand = g_cand + b * HW;

    float gsum = 0.0f; unsigned int gcnt = 0;
    const int TPB = CB * CT;                 // 65536 threads per batch
    const int ITER = (HW / 4) / TPB;         // exactly 2
    int start = blockIdx.x * CT + tid;

    #pragma unroll
    for (int it = 0; it < ITER; it++) {
        float4 v = sc[start + it * TPB];
        float  val[4] = { v.x, v.y, v.z, v.w };
        #pragma unroll
        for (int j = 0; j < 4; j++) {
            unsigned int bits = __float_as_uint(val[j]);
            unsigned int pref = bits >> 21;
            if (pref > key0) { gsum += val[j]; gcnt++; }
            bool eq = (pref == key0);
            unsigned int m = __ballot_sync(0xFFFFFFFFu, eq);
            if (m) {
                int leader = __ffs(m) - 1;
                unsigned int base;
                if (lane == leader) base = atomicAdd(&g_ncand[b], (unsigned int)__popc(m));
                base = __shfl_sync(0xFFFFFFFFu, base, leader);
                if (eq) cand[base + __popc(m & ((1u << lane) - 1u))] = bits;
            }
        }
    }

    // block reduce greater-sum
    #pragma unroll
    for (int off = 16; off > 0; off >>= 1) {
        gsum += __shfl_down_sync(0xFFFFFFFFu, gsum, off);
        gcnt += __shfl_down_sync(0xFFFFFFFFu, gcnt, off);
    }
    if (lane == 0) { s_wsum[tid >> 5] = gsum; s_wcnt[tid >> 5] = gcnt; }
    __syncthreads();
    if (tid == 0) {
        float bs = 0.0f; unsigned int bc = 0;
        #pragma unroll
        for (int w = 0; w < CT / 32; w++) { bs += s_wsum[w]; bc += s_wcnt[w]; }
        if (bs != 0.0f || bc) { atomicAdd(&g_sum[b], bs); atomicAdd(&g_cnt[b], bc); }
    }

    __threadfence();
    __syncthreads();
    if (tid == 0) {
        unsigned int done = atomicAdd(&g_ctr[1 * BATCH + b], 1u);
        s_last = (done == gridDim.x - 1);
    }
    __syncthreads();
    if (!s_last) return;

    // ---- last block: exact top-k over the compacted boundary-bin candidates ----
    unsigned int ncand = __ldcg(&g_ncand[b]);
    unsigned int k1 = g_sel_k[b];            // remaining k within this bin

    // level 1: bits[20:10]
    for (int i = tid; i < 2048; i += CT) s_hist[i] = 0;
    __syncthreads();
    for (unsigned int i = tid; i < ncand; i += CT)
        atomicAdd(&s_hist[(__ldcg(&cand[i]) >> 10) & 0x7FFu], 1u);
    __syncthreads();
    block_select<CT, false>(s_hist, 2048, k1, tid, s_scan, &s_bin, &s_rem);
    __syncthreads();
    unsigned int key1 = s_bin, k2 = s_rem;
    __syncthreads();

    // level 2: bits[9:0] among matching
    for (int i = tid; i < 1024; i += CT) s_hist[i] = 0;
    __syncthreads();
    for (unsigned int i = tid; i < ncand; i += CT) {
        unsigned int bits = __ldcg(&cand[i]);
        if (((bits >> 10) & 0x7FFu) == key1) atomicAdd(&s_hist[bits & 0x3FFu], 1u);
    }
    __syncthreads();
    block_select<CT, false>(s_hist, 1024, k2, tid, s_scan, &s_bin, &s_rem);
    __syncthreads();
    unsigned int vstar = (key0 << 21) | (key1 << 10) | s_bin;

    // sum candidates strictly greater than v*
    float lsum = 0.0f; unsigned int lcnt = 0;
    for (unsigned int i = tid; i < ncand; i += CT) {
        unsigned int bits = __ldcg(&cand[i]);
        if (bits > vstar) { lsum += __uint_as_float(bits); lcnt++; }
    }
    #pragma unroll
    for (int off = 16; off > 0; off >>= 1) {
        lsum += __shfl_down_sync(0xFFFFFFFFu, lsum, off);
        lcnt += __shfl_down_sync(0xFFFFFFFFu, lcnt, off);
    }
    if (lane == 0) { s_wsum[tid >> 5] = lsum; s_wcnt[tid >> 5] = lcnt; }
    __syncthreads();
    if (tid == 0) {
        float cs = 0.0f; unsigned int cc = 0;
        #pragma unroll
        for (int w = 0; w < CT / 32; w++) { cs += s_wsum[w]; cc += s_wcnt[w]; }
        float gtot = __ldcg(&g_sum[b]);
        out[b] = gtot + cs + (float)((int)k1 - (int)cc) * __uint_as_float(vstar);
    }
}

// ---------------- launch ----------------
extern "C" void kernel_launch(void* const* d_in, const int* in_sizes, int n_in,
                              void* d_out, int out_size) {
    const float* logit = (const float*)d_in[0];
    float* out = (float*)d_out;

    k_pixel<<<NPIX / 4 / 256, 256>>>(logit);
    k_region<<<dim3(IMW / TBX, IMH / TBY, BATCH), dim3(TBX, TBY)>>>();
    k_collect<<<dim3(CB, BATCH), CT>>>(out);
}

// round 11
// speedup vs baseline: 2.4622x; 2.4622x over previous
#include <cuda_runtime.h>
#include <cuda_bf16.h>
#include <cstdint>

#define BATCH 4
#define NCLS 19
#define IMH 512
#define IMW 1024
#define HW (IMH * IMW)           // 524288 = 2^19
#define NPIX (BATCH * HW)
#define KTOP 256
#define EPSF 1e-6f

// ---------------- scratch (static device arrays; no allocation) ----------------
__device__ float         g_entropy[NPIX];
__device__ unsigned char g_label[NPIX];
__device__ float         g_score[NPIX];
__device__ unsigned int  g_hist0[BATCH * 2048];
__device__ unsigned int  g_hist1[BATCH * 2048];
__device__ unsigned int  g_hist2[BATCH * 1024];
__device__ float         g_fsum [BATCH * 1024];   // per-level2-bin float sums
__device__ unsigned int  g_sel_key[BATCH];        // level-0 bin (top 11 bits)
__device__ unsigned int  g_sel_k[BATCH];          // remaining k after level 0
__device__ unsigned int  g_key01[BATCH];          // 22-bit prefix after level 1
__device__ unsigned int  g_k2[BATCH];             // remaining k after level 1
__device__ float         g_sum[BATCH];            // sum of values with 22-bit prefix > key01
__device__ unsigned int  g_ctr[3 * BATCH];        // last-block counters per phase

// ---------------- block-wide descending radix-select -------------------------
// Finds bin (scanning from highest down) where cumulative count crosses k.
// Exactly one thread writes *ret_bin/*ret_rem; caller must __syncthreads after.
template<int T, bool LDCG>
__device__ __forceinline__ void block_select(const unsigned int* __restrict__ h,
                                             int nbins, unsigned int k, int tid,
                                             unsigned int* s_scan,      // >= T/32
                                             unsigned int* ret_bin,
                                             unsigned int* ret_rem) {
    const int W = T / 32;
    int cs = nbins / T;
    int base = nbins - 1 - tid * cs;
    unsigned int csum = 0;
    for (int i = 0; i < cs; i++) csum += LDCG ? __ldcg(&h[base - i]) : h[base - i];

    unsigned int v = csum;
    #pragma unroll
    for (int off = 1; off < 32; off <<= 1) {
        unsigned int y = __shfl_up_sync(0xFFFFFFFFu, v, off);
        if ((tid & 31) >= off) v += y;
    }
    if ((tid & 31) == 31) s_scan[tid >> 5] = v;
    __syncthreads();
    if (tid < W) {
        unsigned int w = s_scan[tid];
        const unsigned int m = (W == 32) ? 0xFFFFFFFFu : ((1u << W) - 1u);
        #pragma unroll
        for (int off = 1; off < W; off <<= 1) {
            unsigned int y = __shfl_up_sync(m, w, off);
            if (tid >= off) w += y;
        }
        s_scan[tid] = w;
    }
    __syncthreads();
    unsigned int incl = v + ((tid >= 32) ? s_scan[(tid >> 5) - 1] : 0u);
    unsigned int excl = incl - csum;

    if (excl < k && k <= incl) {
        unsigned int run = excl;
        for (int i = 0; i < cs; i++) {
            unsigned int hv = LDCG ? __ldcg(&h[base - i]) : h[base - i];
            if (run < k && k <= run + hv) {
                *ret_bin = (unsigned int)(base - i);
                *ret_rem = k - run;
                break;
            }
            run += hv;
        }
    }
}

// ---------------- kernel 1: per-pixel entropy + argmax (float4, fused init) ----
__global__ void k_pixel(const float* __restrict__ logit) {
    if (blockIdx.x == 0) {
        int t = threadIdx.x;
        for (int i = t; i < 2048 * BATCH; i += 256) { g_hist0[i] = 0; g_hist1[i] = 0; }
        for (int i = t; i < 1024 * BATCH; i += 256) { g_hist2[i] = 0; g_fsum[i] = 0.0f; }
        if (t < BATCH) { g_sel_k[t] = KTOP; g_sum[t] = 0.0f; }
        if (t < 3 * BATCH) g_ctr[t] = 0;
    }

    int idx = blockIdx.x * blockDim.x + threadIdx.x;   // one float4 (4 pixels)
    int p4 = idx * 4;
    int b  = p4 >> 19;
    int hw = p4 & (HW - 1);
    const float4* base = (const float4*)(logit + (size_t)b * NCLS * HW + hw);
    const int planeStride = HW / 4;

    float4 ent  = make_float4(0.f, 0.f, 0.f, 0.f);
    float4 best = make_float4(-1.f, -1.f, -1.f, -1.f);
    int bc0 = 0, bc1 = 0, bc2 = 0, bc3 = 0;
    #pragma unroll
    for (int c = 0; c < NCLS; c++) {
        float4 p = base[c * planeStride];
        ent.x -= p.x * __logf(p.x + EPSF);
        ent.y -= p.y * __logf(p.y + EPSF);
        ent.z -= p.z * __logf(p.z + EPSF);
        ent.w -= p.w * __logf(p.w + EPSF);
        if (p.x > best.x) { best.x = p.x; bc0 = c; }
        if (p.y > best.y) { best.y = p.y; bc1 = c; }
        if (p.z > best.z) { best.z = p.z; bc2 = c; }
        if (p.w > best.w) { best.w = p.w; bc3 = c; }
    }
    float invLogC = 1.0f / __logf((float)NCLS);
    ent.x *= invLogC; ent.y *= invLogC; ent.z *= invLogC; ent.w *= invLogC;
    ((float4*)g_entropy)[idx] = ent;
    ((uchar4*)g_label)[idx] = make_uchar4((unsigned char)bc0, (unsigned char)bc1,
                                          (unsigned char)bc2, (unsigned char)bc3);
}

// ---------------- kernel 2: 3x3 region score + hist0 + fused select0 ----------
#define TBX 32
#define TBY 8
__global__ void k_region(void) {
    __shared__ float         s_ent[TBY + 2][TBX + 2];
    __shared__ unsigned char s_lab[TBY + 2][TBX + 2];
    __shared__ unsigned int  s_hist[2048];
    __shared__ float         s_T[48];           // impurity table
    __shared__ unsigned int  s_scan[8];
    __shared__ unsigned int  s_bin, s_rem;
    __shared__ int           s_last;

    int b  = blockIdx.z;
    int bx = blockIdx.x * TBX;
    int by = blockIdx.y * TBY;
    int tx = threadIdx.x, ty = threadIdx.y;
    int tid = ty * TBX + tx;

    for (int i = tid; i < 2048; i += 256) s_hist[i] = 0;

    if (tid < 48) {
        int nIdx = tid >> 4, c = tid & 15;
        float n = (nIdx == 0) ? 4.0f : (nIdx == 1) ? 6.0f : 9.0f;
        float val = 0.0f;
        if (c >= 1 && c <= 9) {
            float p = (float)c / n;
            val = -p * __logf(p + EPSF) * (1.0f / __logf((float)NCLS));
        }
        s_T[tid] = val;
    }

    const int TILE = (TBY + 2) * (TBX + 2);
    for (int i = tid; i < TILE; i += 256) {
        int ly = i / (TBX + 2), lx = i % (TBX + 2);
        int gy = by + ly - 1, gx = bx + lx - 1;
        bool ok = (gy >= 0 && gy < IMH && gx >= 0 && gx < IMW);
        int gidx = b * HW + gy * IMW + gx;
        s_ent[ly][lx] = ok ? g_entropy[gidx] : 0.0f;
        s_lab[ly][lx] = ok ? g_label[gidx] : (unsigned char)255;
    }
    __syncthreads();

    float entsum = 0.0f;
    unsigned long long accLo = 0ull;   // classes 0..15, 4-bit counters
    unsigned int accHi = 0u;           // classes 16..18
    int n = 0;
    #pragma unroll
    for (int dy = 0; dy < 3; dy++)
    #pragma unroll
        for (int dx = 0; dx < 3; dx++) {
            entsum += s_ent[ty + dy][tx + dx];
            int L = s_lab[ty + dy][tx + dx];
            if (L < 16)        { accLo += 1ull << (L * 4);        n++; }
            else if (L != 255) { accHi += 1u   << ((L - 16) * 4); n++; }
        }

    int nIdx = (n == 9) ? 2 : ((n == 6) ? 1 : 0);
    const float* T = s_T + nIdx * 16;
    float imp = 0.0f;
    #pragma unroll
    for (int c = 0; c < 16; c++) imp += T[(unsigned int)(accLo >> (c * 4)) & 15u];
    #pragma unroll
    for (int c = 0; c < 3; c++)  imp += T[(accHi >> (c * 4)) & 15u];

    float sc = entsum * (1.0f / 9.0f) * imp;
    g_score[b * HW + (by + ty) * IMW + (bx + tx)] = sc;

    unsigned int bits = __float_as_uint(sc);     // sc >= 0 => uint order == float order
    atomicAdd(&s_hist[bits >> 21], 1u);
    __syncthreads();
    for (int i = tid; i < 2048; i += 256) {
        unsigned int v = s_hist[i];
        if (v) atomicAdd(&g_hist0[b * 2048 + i], v);
    }

    __threadfence();
    __syncthreads();
    if (tid == 0) {
        unsigned int done = atomicAdd(&g_ctr[0 * BATCH + b], 1u);
        s_last = (done == gridDim.x * gridDim.y - 1);
    }
    __syncthreads();
    if (s_last) {
        block_select<256, true>(g_hist0 + b * 2048, 2048, KTOP, tid,
                                s_scan, &s_bin, &s_rem);
        __syncthreads();
        if (tid == 0) { g_sel_key[b] = s_bin; g_sel_k[b] = s_rem; }
    }
}

// ---------------- kernel 3: level-1 histogram + fused select1 -----------------
#define RB 128   // blocks per batch
#define RT 512   // threads per block
__global__ void k_refine1(void) {
    __shared__ unsigned int s_hist[2048];
    __shared__ unsigned int s_scan[RT / 32];
    __shared__ unsigned int s_bin, s_rem;
    __shared__ int s_last;

    int b = blockIdx.y;
    int tid = threadIdx.x;
    unsigned int key0 = g_sel_key[b];
    const float4* sc = (const float4*)(g_score + b * HW);

    for (int i = tid; i < 2048; i += RT) s_hist[i] = 0;
    __syncthreads();

    const int TPB = RB * RT;                 // 65536
    const int ITER = (HW / 4) / TPB;         // 2
    int start = blockIdx.x * RT + tid;
    #pragma unroll
    for (int it = 0; it < ITER; it++) {
        float4 v = sc[start + it * TPB];
        unsigned int bx;
        bx = __float_as_uint(v.x); if ((bx >> 21) == key0) atomicAdd(&s_hist[(bx >> 10) & 0x7FFu], 1u);
        bx = __float_as_uint(v.y); if ((bx >> 21) == key0) atomicAdd(&s_hist[(bx >> 10) & 0x7FFu], 1u);
        bx = __float_as_uint(v.z); if ((bx >> 21) == key0) atomicAdd(&s_hist[(bx >> 10) & 0x7FFu], 1u);
        bx = __float_as_uint(v.w); if ((bx >> 21) == key0) atomicAdd(&s_hist[(bx >> 10) & 0x7FFu], 1u);
    }
    __syncthreads();
    for (int i = tid; i < 2048; i += RT) {
        unsigned int v = s_hist[i];
        if (v) atomicAdd(&g_hist1[b * 2048 + i], v);
    }

    __threadfence();
    __syncthreads();
    if (tid == 0) {
        unsigned int done = atomicAdd(&g_ctr[1 * BATCH + b], 1u);
        s_last = (done == gridDim.x - 1);
    }
    __syncthreads();
    if (s_last) {
        block_select<RT, true>(g_hist1 + b * 2048, 2048, g_sel_k[b], tid,
                               s_scan, &s_bin, &s_rem);
        __syncthreads();
        if (tid == 0) {
            g_key01[b] = (key0 << 11) | s_bin;   // 22-bit prefix
            g_k2[b]    = s_rem;
        }
    }
}

// ---------------- kernel 4: level-2 count+sum histogram + fused finalize ------
__global__ void k_refine2(float* __restrict__ out) {
    __shared__ unsigned int s_cnt[1024];
    __shared__ float        s_fs[1024];
    __shared__ unsigned int s_scan[RT / 32];
    __shared__ float        s_wsum[RT / 32];
    __shared__ unsigned int s_bin, s_rem;
    __shared__ int s_last;

    int b = blockIdx.y;
    int tid = threadIdx.x;
    int lane = tid & 31;
    unsigned int key01 = g_key01[b];
    const float4* sc = (const float4*)(g_score + b * HW);

    for (int i = tid; i < 1024; i += RT) { s_cnt[i] = 0; s_fs[i] = 0.0f; }
    __syncthreads();

    float gsum = 0.0f;
    const int TPB = RB * RT;
    const int ITER = (HW / 4) / TPB;
    int start = blockIdx.x * RT + tid;
    #pragma unroll
    for (int it = 0; it < ITER; it++) {
        float4 v = sc[start + it * TPB];
        float val[4] = { v.x, v.y, v.z, v.w };
        #pragma unroll
        for (int j = 0; j < 4; j++) {
            unsigned int bits = __float_as_uint(val[j]);
            unsigned int pref = bits >> 10;
            if (pref > key01) gsum += val[j];
            else if (pref == key01) {
                unsigned int bin = bits & 0x3FFu;
                atomicAdd(&s_cnt[bin], 1u);
                atomicAdd(&s_fs[bin], val[j]);
            }
        }
    }

    // block reduce gsum -> global
    #pragma unroll
    for (int off = 16; off > 0; off >>= 1)
        gsum += __shfl_down_sync(0xFFFFFFFFu, gsum, off);
    if (lane == 0) s_wsum[tid >> 5] = gsum;
    __syncthreads();
    if (tid == 0) {
        float bs = 0.0f;
        #pragma unroll
        for (int w = 0; w < RT / 32; w++) bs += s_wsum[w];
        if (bs != 0.0f) atomicAdd(&g_sum[b], bs);
    }
    __syncthreads();
    for (int i = tid; i < 1024; i += RT) {
        unsigned int c = s_cnt[i];
        if (c) { atomicAdd(&g_hist2[b * 1024 + i], c); atomicAdd(&g_fsum[b * 1024 + i], s_fs[i]); }
    }

    __threadfence();
    __syncthreads();
    if (tid == 0) {
        unsigned int done = atomicAdd(&g_ctr[2 * BATCH + b], 1u);
        s_last = (done == gridDim.x - 1);
    }
    __syncthreads();
    if (!s_last) return;

    // ---- last block: select level 2 + closed-form finalize ----
    unsigned int k2 = g_k2[b];
    block_select<RT, true>(g_hist2 + b * 1024, 1024, k2, tid, s_scan, &s_bin, &s_rem);
    __syncthreads();
    unsigned int binstar = s_bin, rem = s_rem;

    // sum of per-bin float sums for bins strictly above binstar
    float tail = 0.0f;
    for (int i = tid; i < 1024; i += RT)
        if ((unsigned int)i > binstar) tail += __ldcg(&g_fsum[b * 1024 + i]);
    #pragma unroll
    for (int off = 16; off > 0; off >>= 1)
        tail += __shfl_down_sync(0xFFFFFFFFu, tail, off);
    if (lane == 0) s_wsum[tid >> 5] = tail;
    __syncthreads();
    if (tid == 0) {
        float ts = 0.0f;
        #pragma unroll
        for (int w = 0; w < RT / 32; w++) ts += s_wsum[w];
        // every value in binstar has the exact bit pattern (key01<<10)|binstar
        float vstar = __uint_as_float((key01 << 10) | binstar);
        out[b] = __ldcg(&g_sum[b]) + ts + (float)rem * vstar;
    }
}

// ---------------- launch ----------------
extern "C" void kernel_launch(void* const* d_in, const int* in_sizes, int n_in,
                              void* d_out, int out_size) {
    const float* logit = (const float*)d_in[0];
    float* out = (float*)d_out;

    k_pixel<<<NPIX / 4 / 256, 256>>>(logit);
    k_region<<<dim3(IMW / TBX, IMH / TBY, BATCH), dim3(TBX, TBY)>>>();
    k_refine1<<<dim3(RB, BATCH), RT>>>();
    k_refine2<<<dim3(RB, BATCH), RT>>>(out);
}